// round 5
// baseline (speedup 1.0000x reference)
#include <cuda_runtime.h>
#include <math.h>

#define Bsz   262144
#define Dd    6
#define Hh    100
#define NTHR  256
#define NBLK  (Bsz / NTHR)      /* 1024 */
#define NELEM (Bsz * Dd)

#define RTOLf 1e-7f
#define ATOLf 1e-9f

/* Dopri5 tableau (double-evaluated, cast to f32 — matches JAX's f32 promotion) */
static __device__ __constant__ const float A21f = (float)(1.0/5.0);
static __device__ __constant__ const float A31f = (float)(3.0/40.0),  A32f = (float)(9.0/40.0);
static __device__ __constant__ const float A41f = (float)(44.0/45.0), A42f = (float)(-56.0/15.0), A43f = (float)(32.0/9.0);
static __device__ __constant__ const float A51f = (float)(19372.0/6561.0), A52f = (float)(-25360.0/2187.0),
                                           A53f = (float)(64448.0/6561.0), A54f = (float)(-212.0/729.0);
static __device__ __constant__ const float A61f = (float)(9017.0/3168.0), A62f = (float)(-355.0/33.0),
                                           A63f = (float)(46732.0/5247.0), A64f = (float)(49.0/176.0),
                                           A65f = (float)(-5103.0/18656.0);
static __device__ __constant__ const float B1f = (float)(35.0/384.0), B3f = (float)(500.0/1113.0),
                                           B4f = (float)(125.0/192.0), B5f = (float)(-2187.0/6784.0),
                                           B6f = (float)(11.0/84.0);
static __device__ __constant__ const float E1f = (float)(71.0/57600.0), E3f = (float)(-71.0/16695.0),
                                           E4f = (float)(71.0/1920.0),  E5f = (float)(-17253.0/339200.0),
                                           E6f = (float)(22.0/525.0),   E7f = (float)(-1.0/40.0);

struct ScalarState {
    float t, h, h0, d1;
    int   accept, done;
};
__device__ ScalarState g_sc;

__device__ float g_partA[NBLK];
__device__ float g_partB[NBLK];

/* state buffers, stride 8 floats per element for 16B-aligned vector access */
__device__ float g_y [Bsz * 8];   /* current accepted y  */
__device__ float g_f [Bsz * 8];   /* current accepted f(y) (k1, FSAL) */
__device__ float g_ys[Bsz * 8];   /* staged y_new of last executed step */
__device__ float g_ks[Bsz * 8];   /* staged k7 of last executed step */

/* ---------------- helpers ---------------- */

__device__ __forceinline__ float fast_tanh(float x) {
    /* tanh(x) = 1 - 2/(e^{2x}+1); MUFU.EX2 + MUFU.RCP, ~1e-6 accurate, saturates cleanly */
    float e = __expf(2.0f * x);
    return 1.0f - __fdividef(2.0f, e + 1.0f);
}

__device__ __forceinline__ void ld6(const float* p, float* v) {
    float4 a = *(const float4*)p;
    float2 b = *(const float2*)(p + 4);
    v[0]=a.x; v[1]=a.y; v[2]=a.z; v[3]=a.w; v[4]=b.x; v[5]=b.y;
}
__device__ __forceinline__ void st6(float* p, const float* v) {
    *(float4*)p       = make_float4(v[0], v[1], v[2], v[3]);
    *(float2*)(p + 4) = make_float2(v[4], v[5]);
}

/* shared weight layout: per hidden unit j, 4 float4:
   [0]=W1[j,0..3]  [1]=(W1[j,4],W1[j,5],b1[j],0)  [2]=W2[0..3,j]  [3]=(W2[4,j],W2[5,j],0,0) */
__device__ __forceinline__ void load_weights(float4* sw, float* sb2,
                                             const float* __restrict__ W1,
                                             const float* __restrict__ b1,
                                             const float* __restrict__ W2,
                                             const float* __restrict__ b2) {
    int t = threadIdx.x;
    for (int j = t; j < Hh; j += blockDim.x) {
        sw[j*4+0] = make_float4(W1[j*6+0], W1[j*6+1], W1[j*6+2], W1[j*6+3]);
        sw[j*4+1] = make_float4(W1[j*6+4], W1[j*6+5], b1[j], 0.f);
        sw[j*4+2] = make_float4(W2[0*Hh+j], W2[1*Hh+j], W2[2*Hh+j], W2[3*Hh+j]);
        sw[j*4+3] = make_float4(W2[4*Hh+j], W2[5*Hh+j], 0.f, 0.f);
    }
    if (t < 6) sb2[t] = b2[t];
}

/* f(y) = tanh(y @ W1^T + b1) @ W2^T + b2 */
__device__ __forceinline__ void feval(const float4* __restrict__ sw,
                                      const float*  __restrict__ sb2,
                                      const float* y, float* out) {
    float a0 = sb2[0], a1 = sb2[1], a2 = sb2[2], a3 = sb2[3], a4 = sb2[4], a5 = sb2[5];
#pragma unroll 5
    for (int j = 0; j < Hh; j++) {
        float4 wa = sw[j*4+0];
        float4 wb = sw[j*4+1];
        float pre = fmaf(y[0], wa.x, wb.z);
        pre = fmaf(y[1], wa.y, pre);
        pre = fmaf(y[2], wa.z, pre);
        pre = fmaf(y[3], wa.w, pre);
        pre = fmaf(y[4], wb.x, pre);
        pre = fmaf(y[5], wb.y, pre);
        float th = fast_tanh(pre);
        float4 va = sw[j*4+2];
        float4 vb = sw[j*4+3];
        a0 = fmaf(th, va.x, a0);
        a1 = fmaf(th, va.y, a1);
        a2 = fmaf(th, va.z, a2);
        a3 = fmaf(th, va.w, a3);
        a4 = fmaf(th, vb.x, a4);
        a5 = fmaf(th, vb.y, a5);
    }
    out[0]=a0; out[1]=a1; out[2]=a2; out[3]=a3; out[4]=a4; out[5]=a5;
}

__device__ __forceinline__ void block_reduce2(float a, float b, float* outA, float* outB) {
    __shared__ float rA[NTHR];
    __shared__ float rB[NTHR];
    rA[threadIdx.x] = a; rB[threadIdx.x] = b;
    __syncthreads();
    for (int s = NTHR / 2; s > 0; s >>= 1) {
        if (threadIdx.x < s) {
            rA[threadIdx.x] += rA[threadIdx.x + s];
            rB[threadIdx.x] += rB[threadIdx.x + s];
        }
        __syncthreads();
    }
    if (threadIdx.x == 0) { outA[blockIdx.x] = rA[0]; if (outB) outB[blockIdx.x] = rB[0]; }
}

/* ---------------- prologue ---------------- */

__global__ void __launch_bounds__(NTHR) k_init(const float* __restrict__ seq,
                                               const float* __restrict__ W1, const float* __restrict__ b1,
                                               const float* __restrict__ W2, const float* __restrict__ b2) {
    __shared__ float4 sw[Hh * 4];
    __shared__ float  sb2[8];
    load_weights(sw, sb2, W1, b1, W2, b2);
    __syncthreads();

    int g = blockIdx.x * NTHR + threadIdx.x;
    float y[6], f0[6];
#pragma unroll
    for (int d = 0; d < 6; d++) y[d] = seq[g * 48 + 42 + d];   /* input_seq[:, -1, :], T=8, D=6 */
    feval(sw, sb2, y, f0);

    float s0 = 0.f, s1 = 0.f;
#pragma unroll
    for (int d = 0; d < 6; d++) {
        float sc = ATOLf + RTOLf * fabsf(y[d]);
        float r0 = y[d] / sc;
        float r1 = f0[d] / sc;
        s0 += r0 * r0;
        s1 += r1 * r1;
    }
    int base = g * 8;
    st6(g_y + base, y);
    st6(g_f + base, f0);
    block_reduce2(s0, s1, g_partA, g_partB);
}

__global__ void k_h0() {
    __shared__ float rA[NBLK];
    __shared__ float rB[NBLK];
    int t = threadIdx.x;
    rA[t] = g_partA[t]; rB[t] = g_partB[t];
    __syncthreads();
    for (int s = NBLK / 2; s > 0; s >>= 1) {
        if (t < s) { rA[t] += rA[t + s]; rB[t] += rB[t + s]; }
        __syncthreads();
    }
    if (t == 0) {
        float d0 = sqrtf(rA[0] / (float)NELEM);
        float d1 = sqrtf(rB[0] / (float)NELEM);
        float h0 = (d0 < 1e-5f || d1 < 1e-5f) ? 1e-6f : 0.01f * d0 / fmaxf(d1, 1e-12f);
        g_sc.h0 = h0;
        g_sc.d1 = d1;
    }
}

__global__ void __launch_bounds__(NTHR) k_d2(const float* __restrict__ W1, const float* __restrict__ b1,
                                             const float* __restrict__ W2, const float* __restrict__ b2) {
    __shared__ float4 sw[Hh * 4];
    __shared__ float  sb2[8];
    load_weights(sw, sb2, W1, b1, W2, b2);
    float h0 = g_sc.h0;
    __syncthreads();

    int g = blockIdx.x * NTHR + threadIdx.x;
    int base = g * 8;
    float y[6], f0[6], y1[6], f1[6];
    ld6(g_y + base, y);
    ld6(g_f + base, f0);
#pragma unroll
    for (int d = 0; d < 6; d++) y1[d] = fmaf(h0, f0[d], y[d]);
    feval(sw, sb2, y1, f1);

    float s2 = 0.f;
#pragma unroll
    for (int d = 0; d < 6; d++) {
        float sc = ATOLf + RTOLf * fabsf(y[d]);
        float r = (f1[d] - f0[d]) / sc;
        s2 += r * r;
    }
    block_reduce2(s2, 0.f, g_partA, 0);
}

__global__ void k_hinit() {
    __shared__ float rA[NBLK];
    int t = threadIdx.x;
    rA[t] = g_partA[t];
    __syncthreads();
    for (int s = NBLK / 2; s > 0; s >>= 1) {
        if (t < s) rA[t] += rA[t + s];
        __syncthreads();
    }
    if (t == 0) {
        float h0 = g_sc.h0;
        float d2 = sqrtf(rA[0] / (float)NELEM) / h0;
        float dm = fmaxf(g_sc.d1, d2);
        float h1 = (dm <= 1e-15f) ? fmaxf(1e-6f, h0 * 1e-3f)
                                  : powf(0.01f / fmaxf(dm, 1e-15f), 0.2f);
        float h = fminf(fminf(100.0f * h0, h1), 1.0f);
        g_sc.t = 0.0f;
        g_sc.h = h;
        g_sc.accept = 0;
        g_sc.done = 0;
    }
}

/* ---------------- main step ---------------- */

__global__ void __launch_bounds__(NTHR) k_step(const float* __restrict__ W1, const float* __restrict__ b1,
                                               const float* __restrict__ W2, const float* __restrict__ b2) {
    if (g_sc.done) return;           /* uniform early exit once integration finished */

    __shared__ float4 sw[Hh * 4];
    __shared__ float  sb2[8];
    load_weights(sw, sb2, W1, b1, W2, b2);
    float t = g_sc.t, h = g_sc.h;
    int acc = g_sc.accept;
    __syncthreads();

    float hc = fminf(h, 1.0f - t);
    int g = blockIdx.x * NTHR + threadIdx.x;
    int base = g * 8;

    float y[6], k1[6];
    if (acc) {                       /* fold previous staged step into current */
        ld6(g_ys + base, y);
        ld6(g_ks + base, k1);
        st6(g_y + base, y);
        st6(g_f + base, k1);
    } else {
        ld6(g_y + base, y);
        ld6(g_f + base, k1);
    }

    float yt[6], k2[6], k3[6], k4[6], k5[6], k6[6], k7[6], ynew[6];

#pragma unroll
    for (int d = 0; d < 6; d++) yt[d] = fmaf(hc, A21f * k1[d], y[d]);
    feval(sw, sb2, yt, k2);

#pragma unroll
    for (int d = 0; d < 6; d++) {
        float s = fmaf(A32f, k2[d], A31f * k1[d]);
        yt[d] = fmaf(hc, s, y[d]);
    }
    feval(sw, sb2, yt, k3);

#pragma unroll
    for (int d = 0; d < 6; d++) {
        float s = fmaf(A42f, k2[d], A41f * k1[d]);
        s = fmaf(A43f, k3[d], s);
        yt[d] = fmaf(hc, s, y[d]);
    }
    feval(sw, sb2, yt, k4);

#pragma unroll
    for (int d = 0; d < 6; d++) {
        float s = fmaf(A52f, k2[d], A51f * k1[d]);
        s = fmaf(A53f, k3[d], s);
        s = fmaf(A54f, k4[d], s);
        yt[d] = fmaf(hc, s, y[d]);
    }
    feval(sw, sb2, yt, k5);

#pragma unroll
    for (int d = 0; d < 6; d++) {
        float s = fmaf(A62f, k2[d], A61f * k1[d]);
        s = fmaf(A63f, k3[d], s);
        s = fmaf(A64f, k4[d], s);
        s = fmaf(A65f, k5[d], s);
        yt[d] = fmaf(hc, s, y[d]);
    }
    feval(sw, sb2, yt, k6);

#pragma unroll
    for (int d = 0; d < 6; d++) {
        float s = fmaf(B3f, k3[d], B1f * k1[d]);
        s = fmaf(B4f, k4[d], s);
        s = fmaf(B5f, k5[d], s);
        s = fmaf(B6f, k6[d], s);
        ynew[d] = fmaf(hc, s, y[d]);
    }
    feval(sw, sb2, ynew, k7);

    float local = 0.f;
#pragma unroll
    for (int d = 0; d < 6; d++) {
        float s = fmaf(E3f, k3[d], E1f * k1[d]);
        s = fmaf(E4f, k4[d], s);
        s = fmaf(E5f, k5[d], s);
        s = fmaf(E6f, k6[d], s);
        s = fmaf(E7f, k7[d], s);
        float err = hc * s;
        float sc = ATOLf + RTOLf * fmaxf(fabsf(y[d]), fabsf(ynew[d]));
        float r = err / sc;
        local += r * r;
    }
    st6(g_ys + base, ynew);
    st6(g_ks + base, k7);
    block_reduce2(local, 0.f, g_partA, 0);
}

__global__ void k_fin() {
    __shared__ float rA[NBLK];
    int t = threadIdx.x;
    rA[t] = g_partA[t];
    __syncthreads();
    for (int s = NBLK / 2; s > 0; s >>= 1) {
        if (t < s) rA[t] += rA[t + s];
        __syncthreads();
    }
    if (t == 0 && !g_sc.done) {
        float en = sqrtf(rA[0] / (float)NELEM);
        float tt = g_sc.t, h = g_sc.h;
        float hc = fminf(h, 1.0f - tt);
        int accept = (en <= 1.0f) ? 1 : 0;
        float factor = 0.9f * powf(fmaxf(en, 1e-10f), -0.2f);
        factor = fminf(fmaxf(factor, 0.2f), 10.0f);
        float tn = accept ? (tt + hc) : tt;
        g_sc.t = tn;
        g_sc.h = hc * factor;
        g_sc.accept = accept;
        if (tn >= 1.0f - 1e-12f) g_sc.done = 1;
    }
}

/* ---------------- output ---------------- */

__global__ void __launch_bounds__(NTHR) k_out(const float* __restrict__ Wl,
                                              const float* __restrict__ bl,
                                              float* __restrict__ out) {
    int g = blockIdx.x * NTHR + threadIdx.x;
    int base = g * 8;
    int acc = g_sc.accept;
    const float* src = acc ? g_ys : g_y;   /* final fold of last staged step */
    float v[6];
    ld6(src + base, v);
    float s = __ldg(bl);
#pragma unroll
    for (int d = 0; d < 6; d++) s = fmaf(v[d], __ldg(Wl + d), s);
    out[g] = s;
}

/* ---------------- launch ---------------- */

extern "C" void kernel_launch(void* const* d_in, const int* in_sizes, int n_in,
                              void* d_out, int out_size) {
    const float* seq = (const float*)d_in[0];
    const float* W1  = (const float*)d_in[1];
    const float* b1  = (const float*)d_in[2];
    const float* W2  = (const float*)d_in[3];
    const float* b2  = (const float*)d_in[4];
    const float* Wl  = (const float*)d_in[5];
    const float* bl  = (const float*)d_in[6];
    float* out = (float*)d_out;

    k_init<<<NBLK, NTHR>>>(seq, W1, b1, W2, b2);
    k_h0<<<1, NBLK>>>();
    k_d2<<<NBLK, NTHR>>>(W1, b1, W2, b2);
    k_hinit<<<1, NBLK>>>();

    for (int i = 0; i < 64; i++) {
        k_step<<<NBLK, NTHR>>>(W1, b1, W2, b2);
        k_fin<<<1, NBLK>>>();
    }
    k_out<<<NBLK, NTHR>>>(Wl, bl, out);
}

// round 6
// speedup vs baseline: 1.0110x; 1.0110x over previous
#include <cuda_runtime.h>
#include <math.h>

#define Bsz   262144
#define Dd    6
#define Hh    100
#define NTHR  256
#define NBLK  (Bsz / NTHR)      /* 1024 */
#define NELEM (Bsz * Dd)

#define RTOLf 1e-7f
#define ATOLf 1e-9f

/* Dopri5 tableau (double-evaluated, cast to f32 — matches JAX's f32 promotion) */
static __device__ __constant__ const float A21f = (float)(1.0/5.0);
static __device__ __constant__ const float A31f = (float)(3.0/40.0),  A32f = (float)(9.0/40.0);
static __device__ __constant__ const float A41f = (float)(44.0/45.0), A42f = (float)(-56.0/15.0), A43f = (float)(32.0/9.0);
static __device__ __constant__ const float A51f = (float)(19372.0/6561.0), A52f = (float)(-25360.0/2187.0),
                                           A53f = (float)(64448.0/6561.0), A54f = (float)(-212.0/729.0);
static __device__ __constant__ const float A61f = (float)(9017.0/3168.0), A62f = (float)(-355.0/33.0),
                                           A63f = (float)(46732.0/5247.0), A64f = (float)(49.0/176.0),
                                           A65f = (float)(-5103.0/18656.0);
static __device__ __constant__ const float B1f = (float)(35.0/384.0), B3f = (float)(500.0/1113.0),
                                           B4f = (float)(125.0/192.0), B5f = (float)(-2187.0/6784.0),
                                           B6f = (float)(11.0/84.0);
static __device__ __constant__ const float E1f = (float)(71.0/57600.0), E3f = (float)(-71.0/16695.0),
                                           E4f = (float)(71.0/1920.0),  E5f = (float)(-17253.0/339200.0),
                                           E6f = (float)(22.0/525.0),   E7f = (float)(-1.0/40.0);

struct ScalarState {
    float t, h, h0, d1;
    int   accept, done;
};
__device__ ScalarState g_sc;

__device__ float g_partA[NBLK];
__device__ float g_partB[NBLK];

/* state buffers, stride 8 floats per element for 16B-aligned vector access */
__device__ float g_y [Bsz * 8];   /* current accepted y  */
__device__ float g_f [Bsz * 8];   /* current accepted f(y) (k1, FSAL) */
__device__ float g_ys[Bsz * 8];   /* staged y_new of last executed step */
__device__ float g_ks[Bsz * 8];   /* staged k7 of last executed step */

/* ---------------- helpers ---------------- */

__device__ __forceinline__ float fast_tanh(float x) {
    /* tanh(x) = 1 - 2/(e^{2x}+1); MUFU.EX2 + MUFU.RCP, ~1e-6 accurate, saturates cleanly */
    float e = __expf(2.0f * x);
    return 1.0f - __fdividef(2.0f, e + 1.0f);
}

__device__ __forceinline__ void ld6(const float* p, float* v) {
    float4 a = *(const float4*)p;
    float2 b = *(const float2*)(p + 4);
    v[0]=a.x; v[1]=a.y; v[2]=a.z; v[3]=a.w; v[4]=b.x; v[5]=b.y;
}
__device__ __forceinline__ void st6(float* p, const float* v) {
    *(float4*)p       = make_float4(v[0], v[1], v[2], v[3]);
    *(float2*)(p + 4) = make_float2(v[4], v[5]);
}

/* shared weight layout: per hidden unit j, 4 float4:
   [0]=W1[j,0..3]  [1]=(W1[j,4],W1[j,5],b1[j],0)  [2]=W2[0..3,j]  [3]=(W2[4,j],W2[5,j],0,0) */
__device__ __forceinline__ void load_weights(float4* sw, float* sb2,
                                             const float* __restrict__ W1,
                                             const float* __restrict__ b1,
                                             const float* __restrict__ W2,
                                             const float* __restrict__ b2) {
    int t = threadIdx.x;
    for (int j = t; j < Hh; j += blockDim.x) {
        sw[j*4+0] = make_float4(W1[j*6+0], W1[j*6+1], W1[j*6+2], W1[j*6+3]);
        sw[j*4+1] = make_float4(W1[j*6+4], W1[j*6+5], b1[j], 0.f);
        sw[j*4+2] = make_float4(W2[0*Hh+j], W2[1*Hh+j], W2[2*Hh+j], W2[3*Hh+j]);
        sw[j*4+3] = make_float4(W2[4*Hh+j], W2[5*Hh+j], 0.f, 0.f);
    }
    if (t < 6) sb2[t] = b2[t];
}

/* f(y) = tanh(y @ W1^T + b1) @ W2^T + b2 */
__device__ __forceinline__ void feval(const float4* __restrict__ sw,
                                      const float*  __restrict__ sb2,
                                      const float* y, float* out) {
    float a0 = sb2[0], a1 = sb2[1], a2 = sb2[2], a3 = sb2[3], a4 = sb2[4], a5 = sb2[5];
#pragma unroll 5
    for (int j = 0; j < Hh; j++) {
        float4 wa = sw[j*4+0];
        float4 wb = sw[j*4+1];
        float pre = fmaf(y[0], wa.x, wb.z);
        pre = fmaf(y[1], wa.y, pre);
        pre = fmaf(y[2], wa.z, pre);
        pre = fmaf(y[3], wa.w, pre);
        pre = fmaf(y[4], wb.x, pre);
        pre = fmaf(y[5], wb.y, pre);
        float th = fast_tanh(pre);
        float4 va = sw[j*4+2];
        float4 vb = sw[j*4+3];
        a0 = fmaf(th, va.x, a0);
        a1 = fmaf(th, va.y, a1);
        a2 = fmaf(th, va.z, a2);
        a3 = fmaf(th, va.w, a3);
        a4 = fmaf(th, vb.x, a4);
        a5 = fmaf(th, vb.y, a5);
    }
    out[0]=a0; out[1]=a1; out[2]=a2; out[3]=a3; out[4]=a4; out[5]=a5;
}

__device__ __forceinline__ void block_reduce2(float a, float b, float* outA, float* outB) {
    __shared__ float rA[NTHR];
    __shared__ float rB[NTHR];
    rA[threadIdx.x] = a; rB[threadIdx.x] = b;
    __syncthreads();
    for (int s = NTHR / 2; s > 0; s >>= 1) {
        if (threadIdx.x < s) {
            rA[threadIdx.x] += rA[threadIdx.x + s];
            rB[threadIdx.x] += rB[threadIdx.x + s];
        }
        __syncthreads();
    }
    if (threadIdx.x == 0) { outA[blockIdx.x] = rA[0]; if (outB) outB[blockIdx.x] = rB[0]; }
}

/* ---------------- prologue ---------------- */

__global__ void __launch_bounds__(NTHR) k_init(const float* __restrict__ seq,
                                               const float* __restrict__ W1, const float* __restrict__ b1,
                                               const float* __restrict__ W2, const float* __restrict__ b2) {
    __shared__ float4 sw[Hh * 4];
    __shared__ float  sb2[8];
    load_weights(sw, sb2, W1, b1, W2, b2);
    __syncthreads();

    int g = blockIdx.x * NTHR + threadIdx.x;
    float y[6], f0[6];
#pragma unroll
    for (int d = 0; d < 6; d++) y[d] = seq[g * 48 + 42 + d];   /* input_seq[:, -1, :], T=8, D=6 */
    feval(sw, sb2, y, f0);

    float s0 = 0.f, s1 = 0.f;
#pragma unroll
    for (int d = 0; d < 6; d++) {
        float sc = ATOLf + RTOLf * fabsf(y[d]);
        float r0 = y[d] / sc;
        float r1 = f0[d] / sc;
        s0 += r0 * r0;
        s1 += r1 * r1;
    }
    int base = g * 8;
    st6(g_y + base, y);
    st6(g_f + base, f0);
    block_reduce2(s0, s1, g_partA, g_partB);
}

__global__ void k_h0() {
    __shared__ float rA[NBLK];
    __shared__ float rB[NBLK];
    int t = threadIdx.x;
    rA[t] = g_partA[t]; rB[t] = g_partB[t];
    __syncthreads();
    for (int s = NBLK / 2; s > 0; s >>= 1) {
        if (t < s) { rA[t] += rA[t + s]; rB[t] += rB[t + s]; }
        __syncthreads();
    }
    if (t == 0) {
        float d0 = sqrtf(rA[0] / (float)NELEM);
        float d1 = sqrtf(rB[0] / (float)NELEM);
        float h0 = (d0 < 1e-5f || d1 < 1e-5f) ? 1e-6f : 0.01f * d0 / fmaxf(d1, 1e-12f);
        g_sc.h0 = h0;
        g_sc.d1 = d1;
    }
}

__global__ void __launch_bounds__(NTHR) k_d2(const float* __restrict__ W1, const float* __restrict__ b1,
                                             const float* __restrict__ W2, const float* __restrict__ b2) {
    __shared__ float4 sw[Hh * 4];
    __shared__ float  sb2[8];
    load_weights(sw, sb2, W1, b1, W2, b2);
    float h0 = g_sc.h0;
    __syncthreads();

    int g = blockIdx.x * NTHR + threadIdx.x;
    int base = g * 8;
    float y[6], f0[6], y1[6], f1[6];
    ld6(g_y + base, y);
    ld6(g_f + base, f0);
#pragma unroll
    for (int d = 0; d < 6; d++) y1[d] = fmaf(h0, f0[d], y[d]);
    feval(sw, sb2, y1, f1);

    float s2 = 0.f;
#pragma unroll
    for (int d = 0; d < 6; d++) {
        float sc = ATOLf + RTOLf * fabsf(y[d]);
        float r = (f1[d] - f0[d]) / sc;
        s2 += r * r;
    }
    block_reduce2(s2, 0.f, g_partA, 0);
}

__global__ void k_hinit() {
    __shared__ float rA[NBLK];
    int t = threadIdx.x;
    rA[t] = g_partA[t];
    __syncthreads();
    for (int s = NBLK / 2; s > 0; s >>= 1) {
        if (t < s) rA[t] += rA[t + s];
        __syncthreads();
    }
    if (t == 0) {
        float h0 = g_sc.h0;
        float d2 = sqrtf(rA[0] / (float)NELEM) / h0;
        float dm = fmaxf(g_sc.d1, d2);
        float h1 = (dm <= 1e-15f) ? fmaxf(1e-6f, h0 * 1e-3f)
                                  : powf(0.01f / fmaxf(dm, 1e-15f), 0.2f);
        float h = fminf(fminf(100.0f * h0, h1), 1.0f);
        g_sc.t = 0.0f;
        g_sc.h = h;
        g_sc.accept = 0;
        g_sc.done = 0;
    }
}

/* ---------------- main step ---------------- */

__global__ void __launch_bounds__(NTHR) k_step(const float* __restrict__ W1, const float* __restrict__ b1,
                                               const float* __restrict__ W2, const float* __restrict__ b2) {
    if (g_sc.done) return;           /* uniform early exit once integration finished */

    __shared__ float4 sw[Hh * 4];
    __shared__ float  sb2[8];
    load_weights(sw, sb2, W1, b1, W2, b2);
    float t = g_sc.t, h = g_sc.h;
    int acc = g_sc.accept;
    __syncthreads();

    float hc = fminf(h, 1.0f - t);
    int g = blockIdx.x * NTHR + threadIdx.x;
    int base = g * 8;

    float y[6], k1[6];
    if (acc) {                       /* fold previous staged step into current */
        ld6(g_ys + base, y);
        ld6(g_ks + base, k1);
        st6(g_y + base, y);
        st6(g_f + base, k1);
    } else {
        ld6(g_y + base, y);
        ld6(g_f + base, k1);
    }

    float yt[6], k2[6], k3[6], k4[6], k5[6], k6[6], k7[6], ynew[6];

#pragma unroll
    for (int d = 0; d < 6; d++) yt[d] = fmaf(hc, A21f * k1[d], y[d]);
    feval(sw, sb2, yt, k2);

#pragma unroll
    for (int d = 0; d < 6; d++) {
        float s = fmaf(A32f, k2[d], A31f * k1[d]);
        yt[d] = fmaf(hc, s, y[d]);
    }
    feval(sw, sb2, yt, k3);

#pragma unroll
    for (int d = 0; d < 6; d++) {
        float s = fmaf(A42f, k2[d], A41f * k1[d]);
        s = fmaf(A43f, k3[d], s);
        yt[d] = fmaf(hc, s, y[d]);
    }
    feval(sw, sb2, yt, k4);

#pragma unroll
    for (int d = 0; d < 6; d++) {
        float s = fmaf(A52f, k2[d], A51f * k1[d]);
        s = fmaf(A53f, k3[d], s);
        s = fmaf(A54f, k4[d], s);
        yt[d] = fmaf(hc, s, y[d]);
    }
    feval(sw, sb2, yt, k5);

#pragma unroll
    for (int d = 0; d < 6; d++) {
        float s = fmaf(A62f, k2[d], A61f * k1[d]);
        s = fmaf(A63f, k3[d], s);
        s = fmaf(A64f, k4[d], s);
        s = fmaf(A65f, k5[d], s);
        yt[d] = fmaf(hc, s, y[d]);
    }
    feval(sw, sb2, yt, k6);

#pragma unroll
    for (int d = 0; d < 6; d++) {
        float s = fmaf(B3f, k3[d], B1f * k1[d]);
        s = fmaf(B4f, k4[d], s);
        s = fmaf(B5f, k5[d], s);
        s = fmaf(B6f, k6[d], s);
        ynew[d] = fmaf(hc, s, y[d]);
    }
    feval(sw, sb2, ynew, k7);

    float local = 0.f;
#pragma unroll
    for (int d = 0; d < 6; d++) {
        float s = fmaf(E3f, k3[d], E1f * k1[d]);
        s = fmaf(E4f, k4[d], s);
        s = fmaf(E5f, k5[d], s);
        s = fmaf(E6f, k6[d], s);
        s = fmaf(E7f, k7[d], s);
        float err = hc * s;
        float sc = ATOLf + RTOLf * fmaxf(fabsf(y[d]), fabsf(ynew[d]));
        float r = err / sc;
        local += r * r;
    }
    st6(g_ys + base, ynew);
    st6(g_ks + base, k7);
    block_reduce2(local, 0.f, g_partA, 0);
}

__global__ void k_fin() {
    __shared__ float rA[NBLK];
    int t = threadIdx.x;
    rA[t] = g_partA[t];
    __syncthreads();
    for (int s = NBLK / 2; s > 0; s >>= 1) {
        if (t < s) rA[t] += rA[t + s];
        __syncthreads();
    }
    if (t == 0 && !g_sc.done) {
        float en = sqrtf(rA[0] / (float)NELEM);
        float tt = g_sc.t, h = g_sc.h;
        float hc = fminf(h, 1.0f - tt);
        int accept = (en <= 1.0f) ? 1 : 0;
        float factor = 0.9f * powf(fmaxf(en, 1e-10f), -0.2f);
        factor = fminf(fmaxf(factor, 0.2f), 10.0f);
        float tn = accept ? (tt + hc) : tt;
        g_sc.t = tn;
        g_sc.h = hc * factor;
        g_sc.accept = accept;
        if (tn >= 1.0f - 1e-12f) g_sc.done = 1;
    }
}

/* ---------------- output ---------------- */

__global__ void __launch_bounds__(NTHR) k_out(const float* __restrict__ Wl,
                                              const float* __restrict__ bl,
                                              float* __restrict__ out) {
    int g = blockIdx.x * NTHR + threadIdx.x;
    int base = g * 8;
    int acc = g_sc.accept;
    const float* src = acc ? g_ys : g_y;   /* final fold of last staged step */
    float v[6];
    ld6(src + base, v);
    float s = __ldg(bl);
#pragma unroll
    for (int d = 0; d < 6; d++) s = fmaf(v[d], __ldg(Wl + d), s);
    out[g] = s;
}

/* ---------------- launch ---------------- */

extern "C" void kernel_launch(void* const* d_in, const int* in_sizes, int n_in,
                              void* d_out, int out_size) {
    const float* seq = (const float*)d_in[0];
    const float* W1  = (const float*)d_in[1];
    const float* b1  = (const float*)d_in[2];
    const float* W2  = (const float*)d_in[3];
    const float* b2  = (const float*)d_in[4];
    const float* Wl  = (const float*)d_in[5];
    const float* bl  = (const float*)d_in[6];
    float* out = (float*)d_out;

    k_init<<<NBLK, NTHR>>>(seq, W1, b1, W2, b2);
    k_h0<<<1, NBLK>>>();
    k_d2<<<NBLK, NTHR>>>(W1, b1, W2, b2);
    k_hinit<<<1, NBLK>>>();

    for (int i = 0; i < 64; i++) {
        k_step<<<NBLK, NTHR>>>(W1, b1, W2, b2);
        k_fin<<<1, NBLK>>>();
    }
    k_out<<<NBLK, NTHR>>>(Wl, bl, out);
}